// round 15
// baseline (speedup 1.0000x reference)
#include <cuda_runtime.h>
#include <cuda_fp16.h>
#include <mma.h>
#include <cstddef>
#include <cstdint>

using namespace nvcuda;

#define BB 64
#define TT 512
#define DD 512
#define HH 768
#define NG 3072
#define MMROWS (BB * TT)
#define NCTA 96

// recurrence smem layout (bytes) — R12 champion config
#define LDH 80
#define ST_OFF 122880            // Ws: 768 x 80 halves
#define ST_B 10240               // stage: 64 x 80 halves
#define NSTAGE 4
#define GS_OFF 163840            // Gs: 64 x 68 fp32
#define GS_LD 68
#define BS_OFF 181248
#define SMEM_REC 181504

__device__ float  g_xp[(size_t)2 * MMROWS * NG];
__device__ __half g_h[2][2][BB * HH];
__device__ unsigned g_flag[2][64];      // h-version counters per (dir, jb)

__device__ __forceinline__ float sigmoidf(float x) {
    return 1.0f / (1.0f + __expf(-x));
}
__device__ __forceinline__ uint32_t smem_u32(const void* p) {
    uint32_t a;
    asm("{ .reg .u64 t; cvta.to.shared.u64 t, %1; cvt.u32.u64 %0, t; }" : "=r"(a) : "l"(p));
    return a;
}

// tid0-only: wait until the 4 producers of chunk ckp have version >= target
__device__ __forceinline__ void wait_chunk(int dir, int ckp, unsigned target) {
    volatile unsigned* f = &g_flag[dir][4 * ckp];
#pragma unroll
    for (int q = 0; q < 4; q++) {
        if (f[q] < target) {
            int sp = 0;
            while (f[q] < target) { if (++sp > 256) __nanosleep(20); }
        }
    }
    __threadfence();   // acquire: producers' h stores visible
}

// ---------------------------------------------------------------------------
// init: zero h (parity 0, both dirs) and flags — runs each launch/replay
// ---------------------------------------------------------------------------
__global__ void init_state() {
    int idx = blockIdx.x * 256 + threadIdx.x;
    if (idx < BB * HH) {
        g_h[0][0][idx] = __float2half(0.f);
        g_h[1][0][idx] = __float2half(0.f);
    }
    if (idx < 128) ((unsigned*)g_flag)[idx] = 0u;
}

// ---------------------------------------------------------------------------
// xproj (unchanged, known-good)
// ---------------------------------------------------------------------------
__global__ void __launch_bounds__(256) xproj_kernel(
    const float* __restrict__ seq,
    const float* __restrict__ Wfw,
    const float* __restrict__ Wbw)
{
    const int dir = blockIdx.z;
    const float* W = dir ? Wbw : Wfw;
    float* xp = g_xp + (size_t)dir * MMROWS * NG;
    const int m0 = blockIdx.x * 128;
    const int n0 = blockIdx.y * 64;

    __shared__ __align__(16) float As[128][20];
    __shared__ __align__(16) float Bs[16][68];

    const int tid = threadIdx.x;
    const int w = tid >> 5, wm = w & 3, wn = w >> 2;

    wmma::fragment<wmma::accumulator, 16, 16, 8, float> acc[2][2];
#pragma unroll
    for (int i = 0; i < 2; i++)
#pragma unroll
        for (int j = 0; j < 2; j++) wmma::fill_fragment(acc[i][j], 0.0f);

    float ra[8], rb[4];
#pragma unroll
    for (int e = 0; e < 8; e++) {
        int idx = e * 256 + tid; int r = idx >> 4, c = idx & 15;
        ra[e] = seq[(size_t)(m0 + r) * DD + c];
    }
#pragma unroll
    for (int e = 0; e < 4; e++) {
        int idx = e * 256 + tid; int r = idx >> 6, c = idx & 63;
        rb[e] = W[(size_t)r * NG + n0 + c];
    }

    for (int kt = 0; kt < DD / 16; kt++) {
        __syncthreads();
#pragma unroll
        for (int e = 0; e < 8; e++) {
            int idx = e * 256 + tid; int r = idx >> 4, c = idx & 15;
            As[r][c] = ra[e];
        }
#pragma unroll
        for (int e = 0; e < 4; e++) {
            int idx = e * 256 + tid; int r = idx >> 6, c = idx & 63;
            Bs[r][c] = rb[e];
        }
        __syncthreads();
        if (kt + 1 < DD / 16) {
            int k0 = (kt + 1) * 16;
#pragma unroll
            for (int e = 0; e < 8; e++) {
                int idx = e * 256 + tid; int r = idx >> 4, c = idx & 15;
                ra[e] = seq[(size_t)(m0 + r) * DD + k0 + c];
            }
#pragma unroll
            for (int e = 0; e < 4; e++) {
                int idx = e * 256 + tid; int r = idx >> 6, c = idx & 63;
                rb[e] = W[(size_t)(k0 + r) * NG + n0 + c];
            }
        }
#pragma unroll
        for (int k8 = 0; k8 < 16; k8 += 8) {
            wmma::fragment<wmma::matrix_a, 16, 16, 8, wmma::precision::tf32, wmma::row_major> af[2];
            wmma::fragment<wmma::matrix_b, 16, 16, 8, wmma::precision::tf32, wmma::row_major> bf[2];
#pragma unroll
            for (int fm = 0; fm < 2; fm++) {
                wmma::load_matrix_sync(af[fm], &As[wm * 32 + fm * 16][k8], 20);
#pragma unroll
                for (int i = 0; i < af[fm].num_elements; i++)
                    af[fm].x[i] = wmma::__float_to_tf32(af[fm].x[i]);
            }
#pragma unroll
            for (int fn = 0; fn < 2; fn++) {
                wmma::load_matrix_sync(bf[fn], &Bs[k8][wn * 32 + fn * 16], 68);
#pragma unroll
                for (int i = 0; i < bf[fn].num_elements; i++)
                    bf[fn].x[i] = wmma::__float_to_tf32(bf[fn].x[i]);
            }
#pragma unroll
            for (int fm = 0; fm < 2; fm++)
#pragma unroll
                for (int fn = 0; fn < 2; fn++)
                    wmma::mma_sync(acc[fm][fn], af[fm], bf[fn], acc[fm][fn]);
        }
    }
#pragma unroll
    for (int fm = 0; fm < 2; fm++)
#pragma unroll
        for (int fn = 0; fn < 2; fn++) {
            size_t row = m0 + wm * 32 + fm * 16;
            size_t col = n0 + wn * 32 + fn * 16;
            wmma::store_matrix_sync(xp + row * NG + col, acc[fm][fn], NG,
                                    wmma::mem_row_major);
        }
}

__device__ __forceinline__ void cp16s(uint32_t smem_dst, const void* gmem_src) {
    asm volatile("cp.async.ca.shared.global [%0], [%1], 16;\n"
                 :: "r"(smem_dst), "l"(gmem_src));
}

// ---------------------------------------------------------------------------
// Persistent recurrence: R12 mainloop (fp16 WMMA, K=64 chunks, 12 iters,
// 4 stages), grid barrier replaced by per-(dir,jb) flags waited by tid0 only,
// with per-CTA chunk rotation (start at own jb block) for elastic slack.
// ---------------------------------------------------------------------------
__global__ void __launch_bounds__(512, 1) lstm_persistent(
    const int* __restrict__ seq_len,
    const float* __restrict__ Wfw, const float* __restrict__ bfw,
    const float* __restrict__ Wbw, const float* __restrict__ bbw,
    float* __restrict__ out)
{
    const int dir = blockIdx.x / 48;
    const int jb  = blockIdx.x % 48;
    const float* W    = dir ? Wbw : Wfw;
    const float* bias = dir ? bbw : bfw;
    const float* xp = g_xp + (size_t)dir * MMROWS * NG;
    const int rot = jb >> 2;                       // starting chunk = own block

    extern __shared__ __align__(128) char sm[];
    const uint32_t smb = smem_u32(sm);
    __half* Ws = (__half*)sm;                       // [768][LDH]
    float*  Gs = (float*)(sm + GS_OFF);             // [64][GS_LD]
    float*  bs = (float*)(sm + BS_OFF);             // 64 floats

    const int tid = threadIdx.x;
    const int w  = tid >> 5;
    const int wm = w & 3;      // 16-row (batch) block
    const int wn = w >> 2;     // 16-col (gate) block

    // one-time: W slice -> fp16 smem
    for (int i = tid; i < 768 * 64; i += 512) {
        int k = i >> 6, n = i & 63;
        int g = n >> 4, c = n & 15;
        Ws[k * LDH + n] = __float2half(W[(size_t)(DD + k) * NG + g * HH + jb * 16 + c]);
    }
    if (tid < 64) {
        int g = tid >> 4, c = tid & 15;
        bs[tid] = bias[g * HH + jb * 16 + c];
    }

    // per-thread cell ownership
    const int j  = tid & 15;
    const int jg = jb * 16 + j;
    const int bb0 = tid >> 4;
    const int bb1 = bb0 + 32;
    const int L0 = seq_len[bb0];
    const int L1 = seq_len[bb1];
    float c0 = 0.f, c1 = 0.f, h0 = 0.f, h1 = 0.f;

    // chunk copy mapping: 64 rows x 64 halves (128B/row) = 512 x 16B
    const int cr = tid >> 3;          // row 0..63
    const int cu = tid & 7;           // 16B unit 0..7
    const uint32_t cdst = smb + ST_OFF + (uint32_t)(cr * (LDH * 2) + cu * 16);
    const int csrc = cr * HH + cu * 8;   // halves within a chunk

    __syncthreads();

    for (int t = 0; t < TT; t++) {
        const int parr = t & 1;
        const __half* hsrc = g_h[dir][parr];
        __half* hdst = g_h[dir][parr ^ 1];
        const unsigned tgt = (unsigned)t;          // h version required

        const bool a0 = t < L0, a1 = t < L1;
        const int tx0 = dir ? (a0 ? L0 - 1 - t : t) : t;
        const int tx1 = dir ? (a1 ? L1 - 1 - t : t) : t;
        const float* x0 = xp + ((size_t)bb0 * TT + tx0) * NG + jg;
        const float* x1 = xp + ((size_t)bb1 * TT + tx1) * NG + jg;
        float xv00 = x0[0], xv01 = x0[HH], xv02 = x0[2 * HH], xv03 = x0[3 * HH];
        float xv10 = x1[0], xv11 = x1[HH], xv12 = x1[2 * HH], xv13 = x1[3 * HH];

        wmma::fragment<wmma::accumulator, 16, 16, 16, float> acc;
        wmma::fill_fragment(acc, 0.f);

        // prologue: tid0 waits for the first 4 rotated chunks, then all issue
        if (tid == 0) {
#pragma unroll
            for (int s = 0; s < NSTAGE; s++)
                wait_chunk(dir, (s + rot) % 12, tgt);
        }
        __syncthreads();
#pragma unroll
        for (int s = 0; s < NSTAGE; s++) {
            const int cp = (s + rot) % 12;
            cp16s(cdst + s * ST_B, hsrc + csrc + cp * 64);
            asm volatile("cp.async.commit_group;\n");
        }

        for (int ck = 0; ck < 12; ck++) {
            if (ck < 9)       asm volatile("cp.async.wait_group 3;\n");
            else if (ck == 9) asm volatile("cp.async.wait_group 2;\n");
            else if (ck == 10)asm volatile("cp.async.wait_group 1;\n");
            else              asm volatile("cp.async.wait_group 0;\n");
            __syncthreads();   // chunk (ck+rot)%12 visible to all warps

            const int cp = (ck + rot) % 12;
            const __half* Hst = (const __half*)(sm + ST_OFF + (ck & 3) * ST_B);
#pragma unroll
            for (int k16 = 0; k16 < 4; k16++) {
                wmma::fragment<wmma::matrix_a, 16, 16, 16, half, wmma::row_major> af;
                wmma::load_matrix_sync(af, Hst + (wm * 16) * LDH + k16 * 16, LDH);
                wmma::fragment<wmma::matrix_b, 16, 16, 16, half, wmma::row_major> bf;
                wmma::load_matrix_sync(bf, Ws + (cp * 64 + k16 * 16) * LDH + wn * 16, LDH);
                wmma::mma_sync(acc, af, bf, acc);
            }
            // tid0 secures producers of the refill chunk before sync2
            if (ck + 4 < 12 && tid == 0)
                wait_chunk(dir, (ck + 4 + rot) % 12, tgt);
            __syncthreads();   // readers of stage ck&3 done + flag broadcast

            if (ck + 4 < 12) { // refill the just-consumed stage
                const int cpn = (ck + 4 + rot) % 12;
                cp16s(cdst + (ck & 3) * ST_B, hsrc + csrc + cpn * 64);
                asm volatile("cp.async.commit_group;\n");
            }
        }

        // stage gates
        wmma::store_matrix_sync(Gs + (wm * 16) * GS_LD + wn * 16, acc, GS_LD,
                                wmma::mem_row_major);
        __syncthreads();

        // fused cell update (fp32); h stored fp16
        float nh0, nh1;
        {
            float gi = Gs[bb0 * GS_LD +  0 + j] + xv00 + bs[j];
            float gj = Gs[bb0 * GS_LD + 16 + j] + xv01 + bs[16 + j];
            float gf = Gs[bb0 * GS_LD + 32 + j] + xv02 + bs[32 + j];
            float go = Gs[bb0 * GS_LD + 48 + j] + xv03 + bs[48 + j];
            float nc = c0 * sigmoidf(gf + 1.f) + sigmoidf(gi) * tanhf(gj);
            nh0 = tanhf(nc) * sigmoidf(go);
            if (a0) { c0 = nc; h0 = nh0; }
            hdst[bb0 * HH + jg] = __float2half(h0);
        }
        {
            float gi = Gs[bb1 * GS_LD +  0 + j] + xv10 + bs[j];
            float gj = Gs[bb1 * GS_LD + 16 + j] + xv11 + bs[16 + j];
            float gf = Gs[bb1 * GS_LD + 32 + j] + xv12 + bs[32 + j];
            float go = Gs[bb1 * GS_LD + 48 + j] + xv13 + bs[48 + j];
            float nc = c1 * sigmoidf(gf + 1.f) + sigmoidf(gi) * tanhf(gj);
            nh1 = tanhf(nc) * sigmoidf(go);
            if (a1) { c1 = nc; h1 = nh1; }
            hdst[bb1 * HH + jg] = __float2half(h1);
        }

        // publish h version t+1 (release by tid0), then out stores
        __syncthreads();   // all threads' h stores issued
        if (tid == 0) {
            __threadfence();
            *((volatile unsigned*)&g_flag[dir][jb]) = (unsigned)(t + 1);
        }
        {
            int to0 = (dir && a0) ? (L0 - 1 - t) : t;
            out[((size_t)bb0 * TT + to0) * (2 * HH) + dir * HH + jg] = a0 ? nh0 : 0.f;
            int to1 = (dir && a1) ? (L1 - 1 - t) : t;
            out[((size_t)bb1 * TT + to1) * (2 * HH) + dir * HH + jg] = a1 ? nh1 : 0.f;
        }
        // no grid barrier: next step's flag waits provide all pacing
    }

    out[(size_t)BB * TT * 2 * HH + (size_t)bb0 * 2 * HH + dir * HH + jg] = h0;
    out[(size_t)BB * TT * 2 * HH + (size_t)bb1 * 2 * HH + dir * HH + jg] = h1;
}

// ---------------------------------------------------------------------------
extern "C" void kernel_launch(void* const* d_in, const int* in_sizes, int n_in,
                              void* d_out, int out_size)
{
    const float* seq     = (const float*)d_in[0];
    const int*   seq_len = (const int*)d_in[1];
    const float* Wfw     = (const float*)d_in[2];
    const float* bfw     = (const float*)d_in[3];
    const float* Wbw     = (const float*)d_in[4];
    const float* bbw     = (const float*)d_in[5];
    float* out = (float*)d_out;

    cudaFuncSetAttribute(lstm_persistent,
                         cudaFuncAttributeMaxDynamicSharedMemorySize, SMEM_REC);

    init_state<<<(BB * HH + 255) / 256, 256>>>();

    xproj_kernel<<<dim3(MMROWS / 128, NG / 64, 2), 256>>>(seq, Wfw, Wbw);

    lstm_persistent<<<NCTA, 512, SMEM_REC>>>(seq_len, Wfw, bfw, Wbw, bbw, out);
}

// round 16
// speedup vs baseline: 2.6495x; 2.6495x over previous
#include <cuda_runtime.h>
#include <cuda_fp16.h>
#include <mma.h>
#include <cstddef>
#include <cstdint>

using namespace nvcuda;

#define BB 64
#define TT 512
#define DD 512
#define HH 768
#define NG 3072
#define MMROWS (BB * TT)
#define NCTA 96
#define NCTA_DIR 48

// recurrence smem layout (bytes) — R12 champion config (FROZEN)
#define LDH 80
#define ST_OFF 122880            // Ws: 768 x 80 halves
#define ST_B 10240               // stage: 64 x 80 halves
#define NSTAGE 4
#define GS_OFF 163840            // Gs: 64 x 68 fp32
#define GS_LD 68
#define BS_OFF 181248
#define SMEM_REC 181504

__device__ float  g_xp[(size_t)2 * MMROWS * NG];
__device__ __half g_h[2][2][BB * HH];
__device__ unsigned g_bar_count[2];
__device__ unsigned g_bar_gen[2];

// fp16 staging for xproj inputs
__device__ __half g_seq16[(size_t)MMROWS * DD];     // 33.5 MB
__device__ __half g_w16[2][(size_t)DD * NG];        // 6.3 MB

__device__ __forceinline__ float sigmoidf(float x) {
    return 1.0f / (1.0f + __expf(-x));
}
__device__ __forceinline__ uint32_t smem_u32(const void* p) {
    uint32_t a;
    asm("{ .reg .u64 t; cvta.to.shared.u64 t, %1; cvt.u32.u64 %0, t; }" : "=r"(a) : "l"(p));
    return a;
}

// split per-direction grid barrier (R12, known-good)
__device__ __forceinline__ unsigned bar_arrive(int dir) {
    unsigned gen = *((volatile unsigned*)&g_bar_gen[dir]);
    __threadfence();
    unsigned arr = atomicAdd(&g_bar_count[dir], 1u);
    if (arr == NCTA_DIR - 1) {
        g_bar_count[dir] = 0;
        __threadfence();
        atomicAdd(&g_bar_gen[dir], 1u);
    }
    return gen;
}
__device__ __forceinline__ void bar_wait(int dir, unsigned gen) {
    int spins = 0;
    while (*((volatile unsigned*)&g_bar_gen[dir]) == gen) {
        if (++spins > 64) __nanosleep(20);
    }
    __threadfence();
}

__device__ __forceinline__ void cp16s(uint32_t smem_dst, const void* gmem_src) {
    asm volatile("cp.async.ca.shared.global [%0], [%1], 16;\n"
                 :: "r"(smem_dst), "l"(gmem_src));
}

// ---------------------------------------------------------------------------
// convert: seq and W[0:D,:] (both dirs) -> fp16 scratch. 4 elems/thread.
// ---------------------------------------------------------------------------
__global__ void __launch_bounds__(256) convert_kernel(
    const float* __restrict__ seq,
    const float* __restrict__ Wfw,
    const float* __restrict__ Wbw)
{
    const size_t total1 = (size_t)MMROWS * DD;        // seq elems
    const size_t totalW = (size_t)DD * NG;            // per-dir W slice elems
    size_t base = ((size_t)blockIdx.x * 256 + threadIdx.x) * 4;

    if (base < total1) {
        float4 v = *(const float4*)(seq + base);
        __half2 a = __floats2half2_rn(v.x, v.y);
        __half2 b = __floats2half2_rn(v.z, v.w);
        *(__half2*)(g_seq16 + base) = a;
        *(__half2*)(g_seq16 + base + 2) = b;
        return;
    }
    size_t r = base - total1;
    if (r < 2 * totalW) {
        int dir = (r >= totalW);
        size_t o = dir ? (r - totalW) : r;
        const float* W = dir ? Wbw : Wfw;
        float4 v = *(const float4*)(W + o);
        __half2 a = __floats2half2_rn(v.x, v.y);
        __half2 b = __floats2half2_rn(v.z, v.w);
        *(__half2*)(&g_w16[dir][o]) = a;
        *(__half2*)(&g_w16[dir][o] + 2) = b;
    }
}

// ---------------------------------------------------------------------------
// xproj16: xp[dir][m, n] = seq16[m, :] @ W16_dir[:, n]  (fp16 in, fp32 out)
// CTA tile 128x128, BK=32, double-buffered cp.async, 8 warps (4m x 2n),
// warp tile 32x64 (2x4 fragments m16n16k16).
// ---------------------------------------------------------------------------
__global__ void __launch_bounds__(256) xproj16_kernel()
{
    const int dir = blockIdx.z;
    const __half* Wd = g_w16[dir];
    float* xp = g_xp + (size_t)dir * MMROWS * NG;
    const int m0 = blockIdx.x * 128;
    const int n0 = blockIdx.y * 128;

    __shared__ __align__(16) __half As[2][128][40];   // 32 cols + 8 pad
    __shared__ __align__(16) __half Bs[2][32][136];   // 128 cols + 8 pad

    const int tid = threadIdx.x;
    const int w = tid >> 5;
    const int wm = w & 3;      // m block of 32
    const int wn = w >> 2;     // n block of 64

    const uint32_t asb = smem_u32(&As[0][0][0]);
    const uint32_t bsb = smem_u32(&Bs[0][0][0]);
    const uint32_t asz = 128 * 40 * 2;
    const uint32_t bsz = 32 * 136 * 2;

    // A copy mapping: 128 rows x 64B = 512 x 16B, 2 per thread
    const int ar0 = tid >> 2, ac0 = (tid & 3) * 8;           // unit tid
    const int ar1 = (tid + 256) >> 2, ac1 = ((tid + 256) & 3) * 8;
    // B copy mapping: 32 rows x 256B = 512 x 16B, 2 per thread
    const int br0 = tid >> 4, bc0 = (tid & 15) * 8;
    const int br1 = (tid + 256) >> 4, bc1 = ((tid + 256) & 15) * 8;

    wmma::fragment<wmma::accumulator, 16, 16, 16, float> acc[2][4];
#pragma unroll
    for (int i = 0; i < 2; i++)
#pragma unroll
        for (int jj = 0; jj < 4; jj++) wmma::fill_fragment(acc[i][jj], 0.0f);

    // prologue: load k-tile 0 into buf 0
    {
        const __half* aS = g_seq16 + (size_t)m0 * DD;
        cp16s(asb + (ar0 * 40 + ac0) * 2, aS + (size_t)ar0 * DD + ac0);
        cp16s(asb + (ar1 * 40 + ac1) * 2, aS + (size_t)ar1 * DD + ac1);
        const __half* bS = Wd + n0;
        cp16s(bsb + (br0 * 136 + bc0) * 2, bS + (size_t)br0 * NG + bc0);
        cp16s(bsb + (br1 * 136 + bc1) * 2, bS + (size_t)br1 * NG + bc1);
        asm volatile("cp.async.commit_group;\n");
    }

    for (int kt = 0; kt < DD / 32; kt++) {
        const int p = kt & 1;
        if (kt + 1 < DD / 32) {
            const int q = p ^ 1;
            const int k0 = (kt + 1) * 32;
            const __half* aS = g_seq16 + (size_t)m0 * DD + k0;
            cp16s(asb + q * asz + (ar0 * 40 + ac0) * 2, aS + (size_t)ar0 * DD + ac0);
            cp16s(asb + q * asz + (ar1 * 40 + ac1) * 2, aS + (size_t)ar1 * DD + ac1);
            const __half* bS = Wd + (size_t)k0 * NG + n0;
            cp16s(bsb + q * bsz + (br0 * 136 + bc0) * 2, bS + (size_t)br0 * NG + bc0);
            cp16s(bsb + q * bsz + (br1 * 136 + bc1) * 2, bS + (size_t)br1 * NG + bc1);
            asm volatile("cp.async.commit_group;\n");
            asm volatile("cp.async.wait_group 1;\n");
        } else {
            asm volatile("cp.async.wait_group 0;\n");
        }
        __syncthreads();

#pragma unroll
        for (int k16 = 0; k16 < 2; k16++) {
            wmma::fragment<wmma::matrix_a, 16, 16, 16, half, wmma::row_major> af[2];
            wmma::fragment<wmma::matrix_b, 16, 16, 16, half, wmma::row_major> bf[4];
#pragma unroll
            for (int fm = 0; fm < 2; fm++)
                wmma::load_matrix_sync(af[fm], &As[p][wm * 32 + fm * 16][k16 * 16], 40);
#pragma unroll
            for (int fn = 0; fn < 4; fn++)
                wmma::load_matrix_sync(bf[fn], &Bs[p][k16 * 16][wn * 64 + fn * 16], 136);
#pragma unroll
            for (int fm = 0; fm < 2; fm++)
#pragma unroll
                for (int fn = 0; fn < 4; fn++)
                    wmma::mma_sync(acc[fm][fn], af[fm], bf[fn], acc[fm][fn]);
        }
        __syncthreads();   // reads done before next iter overwrites buf p^1... (buf p reused at kt+2)
    }

#pragma unroll
    for (int fm = 0; fm < 2; fm++)
#pragma unroll
        for (int fn = 0; fn < 4; fn++) {
            size_t row = m0 + wm * 32 + fm * 16;
            size_t col = n0 + wn * 64 + fn * 16;
            wmma::store_matrix_sync(xp + row * NG + col, acc[fm][fn], NG,
                                    wmma::mem_row_major);
        }
}

// ---------------------------------------------------------------------------
// Persistent recurrence — BYTE-IDENTICAL to R12 champion.
// ---------------------------------------------------------------------------
__global__ void __launch_bounds__(512, 1) lstm_persistent(
    const int* __restrict__ seq_len,
    const float* __restrict__ Wfw, const float* __restrict__ bfw,
    const float* __restrict__ Wbw, const float* __restrict__ bbw,
    float* __restrict__ out)
{
    const int dir = blockIdx.x / 48;
    const int jb  = blockIdx.x % 48;
    const float* W    = dir ? Wbw : Wfw;
    const float* bias = dir ? bbw : bfw;
    const float* xp = g_xp + (size_t)dir * MMROWS * NG;

    extern __shared__ __align__(128) char sm[];
    const uint32_t smb = smem_u32(sm);
    __half* Ws = (__half*)sm;                       // [768][LDH]
    float*  Gs = (float*)(sm + GS_OFF);             // [64][GS_LD]
    float*  bs = (float*)(sm + BS_OFF);             // 64 floats
    __shared__ unsigned s_gen;

    const int tid = threadIdx.x;
    const int w  = tid >> 5;
    const int wm = w & 3;      // 16-row (batch) block
    const int wn = w >> 2;     // 16-col (gate) block

    // one-time: W slice -> fp16 smem
    for (int i = tid; i < 768 * 64; i += 512) {
        int k = i >> 6, n = i & 63;
        int g = n >> 4, c = n & 15;
        Ws[k * LDH + n] = __float2half(W[(size_t)(DD + k) * NG + g * HH + jb * 16 + c]);
    }
    if (tid < 64) {
        int g = tid >> 4, c = tid & 15;
        bs[tid] = bias[g * HH + jb * 16 + c];
    }

    // per-thread cell ownership
    const int j  = tid & 15;
    const int jg = jb * 16 + j;
    const int bb0 = tid >> 4;
    const int bb1 = bb0 + 32;
    const int L0 = seq_len[bb0];
    const int L1 = seq_len[bb1];
    float c0 = 0.f, c1 = 0.f, h0 = 0.f, h1 = 0.f;
    g_h[dir][0][bb0 * HH + jg] = __float2half(0.f);
    g_h[dir][0][bb1 * HH + jg] = __float2half(0.f);

    // chunk copy mapping: 64 rows x 64 halves (128B/row) = 512 x 16B
    const int cr = tid >> 3;          // row 0..63
    const int cu = tid & 7;           // 16B unit 0..7
    const uint32_t cdst = smb + ST_OFF + (uint32_t)(cr * (LDH * 2) + cu * 16);
    const int csrc = cr * HH + cu * 8;   // halves

    __syncthreads();
    if (tid == 0) { unsigned g0 = bar_arrive(dir); bar_wait(dir, g0); }
    __syncthreads();

    for (int t = 0; t < TT; t++) {
        const int parr = t & 1;
        const __half* hsrc = g_h[dir][parr];
        __half* hdst = g_h[dir][parr ^ 1];

        const bool a0 = t < L0, a1 = t < L1;
        const int tx0 = dir ? (a0 ? L0 - 1 - t : t) : t;
        const int tx1 = dir ? (a1 ? L1 - 1 - t : t) : t;
        const float* x0 = xp + ((size_t)bb0 * TT + tx0) * NG + jg;
        const float* x1 = xp + ((size_t)bb1 * TT + tx1) * NG + jg;
        float xv00 = x0[0], xv01 = x0[HH], xv02 = x0[2 * HH], xv03 = x0[3 * HH];
        float xv10 = x1[0], xv11 = x1[HH], xv12 = x1[2 * HH], xv13 = x1[3 * HH];

        wmma::fragment<wmma::accumulator, 16, 16, 16, float> acc;
        wmma::fill_fragment(acc, 0.f);

        // prologue: issue chunks 0..3 into stages 0..3
#pragma unroll
        for (int s = 0; s < NSTAGE; s++) {
            cp16s(cdst + s * ST_B, hsrc + csrc + s * 64);
            asm volatile("cp.async.commit_group;\n");
        }

        for (int ck = 0; ck < 12; ck++) {
            if (ck < 9)       asm volatile("cp.async.wait_group 3;\n");
            else if (ck == 9) asm volatile("cp.async.wait_group 2;\n");
            else if (ck == 10)asm volatile("cp.async.wait_group 1;\n");
            else              asm volatile("cp.async.wait_group 0;\n");
            __syncthreads();   // chunk ck visible to all warps

            const __half* Hst = (const __half*)(sm + ST_OFF + (ck & 3) * ST_B);
#pragma unroll
            for (int k16 = 0; k16 < 4; k16++) {
                wmma::fragment<wmma::matrix_a, 16, 16, 16, half, wmma::row_major> af;
                wmma::load_matrix_sync(af, Hst + (wm * 16) * LDH + k16 * 16, LDH);
                wmma::fragment<wmma::matrix_b, 16, 16, 16, half, wmma::row_major> bf;
                wmma::load_matrix_sync(bf, Ws + (ck * 64 + k16 * 16) * LDH + wn * 16, LDH);
                wmma::mma_sync(acc, af, bf, acc);
            }
            __syncthreads();   // readers of stage ck&3 done

            if (ck + 4 < 12) { // refill the just-consumed stage
                cp16s(cdst + (ck & 3) * ST_B, hsrc + csrc + (ck + 4) * 64);
                asm volatile("cp.async.commit_group;\n");
            }
        }

        // stage gates (Gs is its own region; no overlay hazard)
        wmma::store_matrix_sync(Gs + (wm * 16) * GS_LD + wn * 16, acc, GS_LD,
                                wmma::mem_row_major);
        __syncthreads();

        // fused cell update (fp32); h stored fp16 before the arrive fence
        float nh0, nh1;
        {
            float gi = Gs[bb0 * GS_LD +  0 + j] + xv00 + bs[j];
            float gj = Gs[bb0 * GS_LD + 16 + j] + xv01 + bs[16 + j];
            float gf = Gs[bb0 * GS_LD + 32 + j] + xv02 + bs[32 + j];
            float go = Gs[bb0 * GS_LD + 48 + j] + xv03 + bs[48 + j];
            float nc = c0 * sigmoidf(gf + 1.f) + sigmoidf(gi) * tanhf(gj);
            nh0 = tanhf(nc) * sigmoidf(go);
            if (a0) { c0 = nc; h0 = nh0; }
            hdst[bb0 * HH + jg] = __float2half(h0);
        }
        {
            float gi = Gs[bb1 * GS_LD +  0 + j] + xv10 + bs[j];
            float gj = Gs[bb1 * GS_LD + 16 + j] + xv11 + bs[16 + j];
            float gf = Gs[bb1 * GS_LD + 32 + j] + xv12 + bs[32 + j];
            float go = Gs[bb1 * GS_LD + 48 + j] + xv13 + bs[48 + j];
            float nc = c1 * sigmoidf(gf + 1.f) + sigmoidf(gi) * tanhf(gj);
            nh1 = tanhf(nc) * sigmoidf(go);
            if (a1) { c1 = nc; h1 = nh1; }
            hdst[bb1 * HH + jg] = __float2half(h1);
        }

        __syncthreads();
        if (tid == 0) s_gen = bar_arrive(dir);   // fence covers h stores only
        {
            int to0 = (dir && a0) ? (L0 - 1 - t) : t;
            out[((size_t)bb0 * TT + to0) * (2 * HH) + dir * HH + jg] = a0 ? nh0 : 0.f;
            int to1 = (dir && a1) ? (L1 - 1 - t) : t;
            out[((size_t)bb1 * TT + to1) * (2 * HH) + dir * HH + jg] = a1 ? nh1 : 0.f;
        }
        if (tid == 0) bar_wait(dir, s_gen);
        __syncthreads();
    }

    out[(size_t)BB * TT * 2 * HH + (size_t)bb0 * 2 * HH + dir * HH + jg] = h0;
    out[(size_t)BB * TT * 2 * HH + (size_t)bb1 * 2 * HH + dir * HH + jg] = h1;
}

// ---------------------------------------------------------------------------
extern "C" void kernel_launch(void* const* d_in, const int* in_sizes, int n_in,
                              void* d_out, int out_size)
{
    const float* seq     = (const float*)d_in[0];
    const int*   seq_len = (const int*)d_in[1];
    const float* Wfw     = (const float*)d_in[2];
    const float* bfw     = (const float*)d_in[3];
    const float* Wbw     = (const float*)d_in[4];
    const float* bbw     = (const float*)d_in[5];
    float* out = (float*)d_out;

    cudaFuncSetAttribute(lstm_persistent,
                         cudaFuncAttributeMaxDynamicSharedMemorySize, SMEM_REC);

    // fp32 -> fp16 staging (seq + input-projection W slices)
    const size_t conv_elems = (size_t)MMROWS * DD + 2 * (size_t)DD * NG;
    convert_kernel<<<(unsigned)((conv_elems / 4 + 255) / 256), 256>>>(seq, Wfw, Wbw);

    // fp16 input projection
    xproj16_kernel<<<dim3(MMROWS / 128, NG / 128, 2), 256>>>();

    // recurrence (frozen R12)
    lstm_persistent<<<NCTA, 512, SMEM_REC>>>(seq_len, Wfw, bfw, Wbw, bbw, out);
}

// round 17
// speedup vs baseline: 2.6546x; 1.0019x over previous
#include <cuda_runtime.h>
#include <cuda_fp16.h>
#include <mma.h>
#include <cstddef>
#include <cstdint>

using namespace nvcuda;

#define BB 64
#define TT 512
#define DD 512
#define HH 768
#define NG 3072
#define MMROWS (BB * TT)
#define NCTA 96
#define NCTA_DIR 48

// recurrence smem layout (bytes) — R12 champion config
#define LDH 80
#define ST_OFF 122880            // Ws: 768 x 80 halves
#define ST_B 10240               // stage: 64 x 80 halves
#define NSTAGE 4
#define GS_OFF 163840            // Gs: 64 x 68 fp32
#define GS_LD 68
#define BS_OFF 181248
#define SMEM_REC 181504

__device__ float  g_xp[(size_t)2 * MMROWS * NG];
__device__ __half g_h[2][2][BB * HH];
__device__ unsigned g_bar_count[2];
__device__ unsigned g_bar_gen[2];

// fp16 staging for xproj inputs
__device__ __half g_seq16[(size_t)MMROWS * DD];     // 33.5 MB
__device__ __half g_w16[2][(size_t)DD * NG];        // 6.3 MB

__device__ __forceinline__ float sigmoidf(float x) {
    return 1.0f / (1.0f + __expf(-x));
}
// fast tanh: exact at +-inf, ~1e-6 relative error via __expf
__device__ __forceinline__ float tanh_fast(float x) {
    return 1.0f - 2.0f / (__expf(2.0f * x) + 1.0f);
}
__device__ __forceinline__ uint32_t smem_u32(const void* p) {
    uint32_t a;
    asm("{ .reg .u64 t; cvta.to.shared.u64 t, %1; cvt.u32.u64 %0, t; }" : "=r"(a) : "l"(p));
    return a;
}

// split per-direction grid barrier (known-good)
__device__ __forceinline__ unsigned bar_arrive(int dir) {
    unsigned gen = *((volatile unsigned*)&g_bar_gen[dir]);
    __threadfence();
    unsigned arr = atomicAdd(&g_bar_count[dir], 1u);
    if (arr == NCTA_DIR - 1) {
        g_bar_count[dir] = 0;
        __threadfence();
        atomicAdd(&g_bar_gen[dir], 1u);
    }
    return gen;
}
__device__ __forceinline__ void bar_wait(int dir, unsigned gen) {
    int spins = 0;
    while (*((volatile unsigned*)&g_bar_gen[dir]) == gen) {
        if (++spins > 64) __nanosleep(20);
    }
    __threadfence();
}

__device__ __forceinline__ void cp16s(uint32_t smem_dst, const void* gmem_src) {
    asm volatile("cp.async.ca.shared.global [%0], [%1], 16;\n"
                 :: "r"(smem_dst), "l"(gmem_src));
}

// ---------------------------------------------------------------------------
// convert: seq and W[0:D,:] (both dirs) -> fp16 scratch (unchanged, known-good)
// ---------------------------------------------------------------------------
__global__ void __launch_bounds__(256) convert_kernel(
    const float* __restrict__ seq,
    const float* __restrict__ Wfw,
    const float* __restrict__ Wbw)
{
    const size_t total1 = (size_t)MMROWS * DD;
    const size_t totalW = (size_t)DD * NG;
    size_t base = ((size_t)blockIdx.x * 256 + threadIdx.x) * 4;

    if (base < total1) {
        float4 v = *(const float4*)(seq + base);
        __half2 a = __floats2half2_rn(v.x, v.y);
        __half2 b = __floats2half2_rn(v.z, v.w);
        *(__half2*)(g_seq16 + base) = a;
        *(__half2*)(g_seq16 + base + 2) = b;
        return;
    }
    size_t r = base - total1;
    if (r < 2 * totalW) {
        int dir = (r >= totalW);
        size_t o = dir ? (r - totalW) : r;
        const float* W = dir ? Wbw : Wfw;
        float4 v = *(const float4*)(W + o);
        __half2 a = __floats2half2_rn(v.x, v.y);
        __half2 b = __floats2half2_rn(v.z, v.w);
        *(__half2*)(&g_w16[dir][o]) = a;
        *(__half2*)(&g_w16[dir][o] + 2) = b;
    }
}

// ---------------------------------------------------------------------------
// xproj16 (unchanged, known-good R16 winner)
// ---------------------------------------------------------------------------
__global__ void __launch_bounds__(256) xproj16_kernel()
{
    const int dir = blockIdx.z;
    const __half* Wd = g_w16[dir];
    float* xp = g_xp + (size_t)dir * MMROWS * NG;
    const int m0 = blockIdx.x * 128;
    const int n0 = blockIdx.y * 128;

    __shared__ __align__(16) __half As[2][128][40];
    __shared__ __align__(16) __half Bs[2][32][136];

    const int tid = threadIdx.x;
    const int w = tid >> 5;
    const int wm = w & 3;
    const int wn = w >> 2;

    const uint32_t asb = smem_u32(&As[0][0][0]);
    const uint32_t bsb = smem_u32(&Bs[0][0][0]);
    const uint32_t asz = 128 * 40 * 2;
    const uint32_t bsz = 32 * 136 * 2;

    const int ar0 = tid >> 2, ac0 = (tid & 3) * 8;
    const int ar1 = (tid + 256) >> 2, ac1 = ((tid + 256) & 3) * 8;
    const int br0 = tid >> 4, bc0 = (tid & 15) * 8;
    const int br1 = (tid + 256) >> 4, bc1 = ((tid + 256) & 15) * 8;

    wmma::fragment<wmma::accumulator, 16, 16, 16, float> acc[2][4];
#pragma unroll
    for (int i = 0; i < 2; i++)
#pragma unroll
        for (int jj = 0; jj < 4; jj++) wmma::fill_fragment(acc[i][jj], 0.0f);

    {
        const __half* aS = g_seq16 + (size_t)m0 * DD;
        cp16s(asb + (ar0 * 40 + ac0) * 2, aS + (size_t)ar0 * DD + ac0);
        cp16s(asb + (ar1 * 40 + ac1) * 2, aS + (size_t)ar1 * DD + ac1);
        const __half* bS = Wd + n0;
        cp16s(bsb + (br0 * 136 + bc0) * 2, bS + (size_t)br0 * NG + bc0);
        cp16s(bsb + (br1 * 136 + bc1) * 2, bS + (size_t)br1 * NG + bc1);
        asm volatile("cp.async.commit_group;\n");
    }

    for (int kt = 0; kt < DD / 32; kt++) {
        const int p = kt & 1;
        if (kt + 1 < DD / 32) {
            const int q = p ^ 1;
            const int k0 = (kt + 1) * 32;
            const __half* aS = g_seq16 + (size_t)m0 * DD + k0;
            cp16s(asb + q * asz + (ar0 * 40 + ac0) * 2, aS + (size_t)ar0 * DD + ac0);
            cp16s(asb + q * asz + (ar1 * 40 + ac1) * 2, aS + (size_t)ar1 * DD + ac1);
            const __half* bS = Wd + (size_t)k0 * NG + n0;
            cp16s(bsb + q * bsz + (br0 * 136 + bc0) * 2, bS + (size_t)br0 * NG + bc0);
            cp16s(bsb + q * bsz + (br1 * 136 + bc1) * 2, bS + (size_t)br1 * NG + bc1);
            asm volatile("cp.async.commit_group;\n");
            asm volatile("cp.async.wait_group 1;\n");
        } else {
            asm volatile("cp.async.wait_group 0;\n");
        }
        __syncthreads();

#pragma unroll
        for (int k16 = 0; k16 < 2; k16++) {
            wmma::fragment<wmma::matrix_a, 16, 16, 16, half, wmma::row_major> af[2];
            wmma::fragment<wmma::matrix_b, 16, 16, 16, half, wmma::row_major> bf[4];
#pragma unroll
            for (int fm = 0; fm < 2; fm++)
                wmma::load_matrix_sync(af[fm], &As[p][wm * 32 + fm * 16][k16 * 16], 40);
#pragma unroll
            for (int fn = 0; fn < 4; fn++)
                wmma::load_matrix_sync(bf[fn], &Bs[p][k16 * 16][wn * 64 + fn * 16], 136);
#pragma unroll
            for (int fm = 0; fm < 2; fm++)
#pragma unroll
                for (int fn = 0; fn < 4; fn++)
                    wmma::mma_sync(acc[fm][fn], af[fm], bf[fn], acc[fm][fn]);
        }
        __syncthreads();
    }

#pragma unroll
    for (int fm = 0; fm < 2; fm++)
#pragma unroll
        for (int fn = 0; fn < 4; fn++) {
            size_t row = m0 + wm * 32 + fm * 16;
            size_t col = n0 + wn * 64 + fn * 16;
            wmma::store_matrix_sync(xp + row * NG + col, acc[fm][fn], NG,
                                    wmma::mem_row_major);
        }
}

// ---------------------------------------------------------------------------
// Persistent recurrence: R12/R16 champion, with (1) single-sync 4-stage
// mainloop (12 syncs/step instead of 24) and (2) tanh_fast in the tail.
// ---------------------------------------------------------------------------
__global__ void __launch_bounds__(512, 1) lstm_persistent(
    const int* __restrict__ seq_len,
    const float* __restrict__ Wfw, const float* __restrict__ bfw,
    const float* __restrict__ Wbw, const float* __restrict__ bbw,
    float* __restrict__ out)
{
    const int dir = blockIdx.x / 48;
    const int jb  = blockIdx.x % 48;
    const float* W    = dir ? Wbw : Wfw;
    const float* bias = dir ? bbw : bfw;
    const float* xp = g_xp + (size_t)dir * MMROWS * NG;

    extern __shared__ __align__(128) char sm[];
    const uint32_t smb = smem_u32(sm);
    __half* Ws = (__half*)sm;                       // [768][LDH]
    float*  Gs = (float*)(sm + GS_OFF);             // [64][GS_LD]
    float*  bs = (float*)(sm + BS_OFF);             // 64 floats
    __shared__ unsigned s_gen;

    const int tid = threadIdx.x;
    const int w  = tid >> 5;
    const int wm = w & 3;      // 16-row (batch) block
    const int wn = w >> 2;     // 16-col (gate) block

    // one-time: W slice -> fp16 smem
    for (int i = tid; i < 768 * 64; i += 512) {
        int k = i >> 6, n = i & 63;
        int g = n >> 4, c = n & 15;
        Ws[k * LDH + n] = __float2half(W[(size_t)(DD + k) * NG + g * HH + jb * 16 + c]);
    }
    if (tid < 64) {
        int g = tid >> 4, c = tid & 15;
        bs[tid] = bias[g * HH + jb * 16 + c];
    }

    // per-thread cell ownership
    const int j  = tid & 15;
    const int jg = jb * 16 + j;
    const int bb0 = tid >> 4;
    const int bb1 = bb0 + 32;
    const int L0 = seq_len[bb0];
    const int L1 = seq_len[bb1];
    float c0 = 0.f, c1 = 0.f, h0 = 0.f, h1 = 0.f;
    g_h[dir][0][bb0 * HH + jg] = __float2half(0.f);
    g_h[dir][0][bb1 * HH + jg] = __float2half(0.f);

    // chunk copy mapping: 64 rows x 64 halves (128B/row) = 512 x 16B
    const int cr = tid >> 3;
    const int cu = tid & 7;
    const uint32_t cdst = smb + ST_OFF + (uint32_t)(cr * (LDH * 2) + cu * 16);
    const int csrc = cr * HH + cu * 8;   // halves

    __syncthreads();
    if (tid == 0) { unsigned g0 = bar_arrive(dir); bar_wait(dir, g0); }
    __syncthreads();

    for (int t = 0; t < TT; t++) {
        const int parr = t & 1;
        const __half* hsrc = g_h[dir][parr];
        __half* hdst = g_h[dir][parr ^ 1];

        const bool a0 = t < L0, a1 = t < L1;
        const int tx0 = dir ? (a0 ? L0 - 1 - t : t) : t;
        const int tx1 = dir ? (a1 ? L1 - 1 - t : t) : t;
        const float* x0 = xp + ((size_t)bb0 * TT + tx0) * NG + jg;
        const float* x1 = xp + ((size_t)bb1 * TT + tx1) * NG + jg;
        float xv00 = x0[0], xv01 = x0[HH], xv02 = x0[2 * HH], xv03 = x0[3 * HH];
        float xv10 = x1[0], xv11 = x1[HH], xv12 = x1[2 * HH], xv13 = x1[3 * HH];

        wmma::fragment<wmma::accumulator, 16, 16, 16, float> acc;
        wmma::fill_fragment(acc, 0.f);

        // prologue: issue chunks 0..2 into stages 0..2
#pragma unroll
        for (int s = 0; s < 3; s++) {
            cp16s(cdst + s * ST_B, hsrc + csrc + s * 64);
            asm volatile("cp.async.commit_group;\n");
        }

        // single-sync mainloop: 4 stages, prefetch distance 3
        for (int ck = 0; ck < 12; ck++) {
            asm volatile("cp.async.wait_group 2;\n");   // chunk ck arrived
            __syncthreads();   // all see chunk ck; readers of ck-1 done

            if (ck + 3 < 12) { // refill just-freed stage (ck+3)&3 == (ck-1)&3
                cp16s(cdst + ((ck + 3) & 3) * ST_B, hsrc + csrc + (ck + 3) * 64);
            }
            asm volatile("cp.async.commit_group;\n");   // commit even if empty

            const __half* Hst = (const __half*)(sm + ST_OFF + (ck & 3) * ST_B);
#pragma unroll
            for (int k16 = 0; k16 < 4; k16++) {
                wmma::fragment<wmma::matrix_a, 16, 16, 16, half, wmma::row_major> af;
                wmma::load_matrix_sync(af, Hst + (wm * 16) * LDH + k16 * 16, LDH);
                wmma::fragment<wmma::matrix_b, 16, 16, 16, half, wmma::row_major> bf;
                wmma::load_matrix_sync(bf, Ws + (ck * 64 + k16 * 16) * LDH + wn * 16, LDH);
                wmma::mma_sync(acc, af, bf, acc);
            }
        }

        __syncthreads();   // all fragment reads done
        wmma::store_matrix_sync(Gs + (wm * 16) * GS_LD + wn * 16, acc, GS_LD,
                                wmma::mem_row_major);
        __syncthreads();

        // fused cell update (fp32, tanh_fast); h stored fp16
        float nh0, nh1;
        {
            float gi = Gs[bb0 * GS_LD +  0 + j] + xv00 + bs[j];
            float gj = Gs[bb0 * GS_LD + 16 + j] + xv01 + bs[16 + j];
            float gf = Gs[bb0 * GS_LD + 32 + j] + xv02 + bs[32 + j];
            float go = Gs[bb0 * GS_LD + 48 + j] + xv03 + bs[48 + j];
            float nc = c0 * sigmoidf(gf + 1.f) + sigmoidf(gi) * tanh_fast(gj);
            nh0 = tanh_fast(nc) * sigmoidf(go);
            if (a0) { c0 = nc; h0 = nh0; }
            hdst[bb0 * HH + jg] = __float2half(h0);
        }
        {
            float gi = Gs[bb1 * GS_LD +  0 + j] + xv10 + bs[j];
            float gj = Gs[bb1 * GS_LD + 16 + j] + xv11 + bs[16 + j];
            float gf = Gs[bb1 * GS_LD + 32 + j] + xv12 + bs[32 + j];
            float go = Gs[bb1 * GS_LD + 48 + j] + xv13 + bs[48 + j];
            float nc = c1 * sigmoidf(gf + 1.f) + sigmoidf(gi) * tanh_fast(gj);
            nh1 = tanh_fast(nc) * sigmoidf(go);
            if (a1) { c1 = nc; h1 = nh1; }
            hdst[bb1 * HH + jg] = __float2half(h1);
        }

        __syncthreads();
        if (tid == 0) s_gen = bar_arrive(dir);   // fence covers h stores only
        {
            int to0 = (dir && a0) ? (L0 - 1 - t) : t;
            out[((size_t)bb0 * TT + to0) * (2 * HH) + dir * HH + jg] = a0 ? nh0 : 0.f;
            int to1 = (dir && a1) ? (L1 - 1 - t) : t;
            out[((size_t)bb1 * TT + to1) * (2 * HH) + dir * HH + jg] = a1 ? nh1 : 0.f;
        }
        if (tid == 0) bar_wait(dir, s_gen);
        __syncthreads();
    }

    out[(size_t)BB * TT * 2 * HH + (size_t)bb0 * 2 * HH + dir * HH + jg] = h0;
    out[(size_t)BB * TT * 2 * HH + (size_t)bb1 * 2 * HH + dir * HH + jg] = h1;
}

// ---------------------------------------------------------------------------
extern "C" void kernel_launch(void* const* d_in, const int* in_sizes, int n_in,
                              void* d_out, int out_size)
{
    const float* seq     = (const float*)d_in[0];
    const int*   seq_len = (const int*)d_in[1];
    const float* Wfw     = (const float*)d_in[2];
    const float* bfw     = (const float*)d_in[3];
    const float* Wbw     = (const float*)d_in[4];
    const float* bbw     = (const float*)d_in[5];
    float* out = (float*)d_out;

    cudaFuncSetAttribute(lstm_persistent,
                         cudaFuncAttributeMaxDynamicSharedMemorySize, SMEM_REC);

    const size_t conv_elems = (size_t)MMROWS * DD + 2 * (size_t)DD * NG;
    convert_kernel<<<(unsigned)((conv_elems / 4 + 255) / 256), 256>>>(seq, Wfw, Wbw);

    xproj16_kernel<<<dim3(MMROWS / 128, NG / 128, 2), 256>>>();

    lstm_persistent<<<NCTA, 512, SMEM_REC>>>(seq_len, Wfw, bfw, Wbw, bbw, out);
}